// round 10
// baseline (speedup 1.0000x reference)
#include <cuda_runtime.h>
#include <cstdint>
#include <math.h>

// Problem constants
#define O_NODES 10000
#define T_EDGES 50000
#define HH      512
#define NG      2048
#define HIST_SZ 131072

// ---------------- scratch (__device__ globals) --------------------------------
__device__ float g_cur [(size_t)T_EDGES * 384];
__device__ float g_mid [(size_t)T_EDGES * HH];
__device__ float g_newt[(size_t)T_EDGES * 1152];
__device__ float g_gxs [(size_t)T_EDGES * NG];
__device__ float g_gxo [(size_t)T_EDGES * NG];
__device__ float g_hsA [(size_t)O_NODES * HH];    // h ping-pong buffer 0 (tf32-rounded)
__device__ float g_hsB [(size_t)O_NODES * HH];    // h ping-pong buffer 1
__device__ float g_cs  [(size_t)O_NODES * HH];    // full fp32 c state
__device__ float g_prev[(size_t)O_NODES * HH];
__device__ float g_pc  [(size_t)O_NODES * 1024];
__device__ float g_obj32[(size_t)O_NODES * 128];
// tf32-rounded weights (Wih/Whh rows gate-permuted)
__device__ float g_w1r   [512  * 384];
__device__ float g_w2r   [1152 * 512];
__device__ float g_wihr  [2048 * 512];
__device__ float g_whhr  [2048 * 512];
__device__ float g_wprojr[512  * 128];
__device__ float g_woutr [128  * 1024];
__device__ float g_bias  [2048];                  // permuted bih+bhh
__device__ float g_h1[512];
__device__ float g_c1[512];
// sort scratch
__device__ int g_hist[HIST_SZ];
__device__ int g_cursor[HIST_SZ];
__device__ int g_cnt[HIST_SZ];
__device__ int g_order[O_NODES];
__device__ int g_pos[O_NODES];

// ---------------- helpers ------------------------------------------------------
__device__ __forceinline__ float roundtf(float x) {
    unsigned u;
    asm("cvt.rna.tf32.f32 %0, %1;" : "=r"(u) : "f"(x));
    return __uint_as_float(u);
}
__device__ __forceinline__ float sigm(float x) { return 1.f / (1.f + expf(-x)); }

__device__ __forceinline__ void mma_tf32(float* d,
                                         unsigned a0, unsigned a1, unsigned a2, unsigned a3,
                                         unsigned b0, unsigned b1) {
    asm volatile(
        "mma.sync.aligned.m16n8k8.row.col.f32.tf32.tf32.f32 "
        "{%0,%1,%2,%3}, {%4,%5,%6,%7}, {%8,%9}, {%0,%1,%2,%3};\n"
        : "+f"(d[0]), "+f"(d[1]), "+f"(d[2]), "+f"(d[3])
        : "r"(a0), "r"(a1), "r"(a2), "r"(a3), "r"(b0), "r"(b1));
}
__device__ __forceinline__ void ldm4(unsigned* r, unsigned addr) {
    asm volatile("ldmatrix.sync.aligned.m8n8.x4.shared.b16 {%0,%1,%2,%3}, [%4];"
                 : "=r"(r[0]), "=r"(r[1]), "=r"(r[2]), "=r"(r[3]) : "r"(addr));
}
__device__ __forceinline__ void cpa16(unsigned sdst, const float* gsrc, int src_bytes) {
    asm volatile("cp.async.cg.shared.global [%0], [%1], 16, %2;\n"
                 :: "r"(sdst), "l"(gsrc), "r"(src_bytes) : "memory");
}
__device__ __forceinline__ void cpa_commit() {
    asm volatile("cp.async.commit_group;\n" ::: "memory");
}
template<int N>
__device__ __forceinline__ void cpa_wait() {
    asm volatile("cp.async.wait_group %0;\n" :: "n"(N) : "memory");
}

// ---------------- tf32 tensor-core GEMM ----------------------------------------
// C[M,N] = epi(A[M,K] @ B[N,K]^T). Inputs pre-rounded to tf32.
// Block 128x128, 4 warps x (64x64), BK=32 per stage, 2-stage cp.async.
// Fragments loaded with ldmatrix.x4 (tf32 frag map == b16 ldmatrix word map).
// Dynamic smem: 2 stages x (A 128x36 + B 128x36) floats = 73728 B -> 2 CTAs/SM.
// EPI: 0 exact(+bias) | 1 relu+round(+bias) | 2 relu, round except cols[512,640)
//      3 round(+bias) | 4 fused LSTM gate epilogue (writes hout, not C)
#define PITCH   36
#define ASTG    (128 * PITCH)          // floats per A stage
#define TG_SMEM (4 * ASTG * 4)         // bytes: 2 stages x (A+B)

template<int EPI, bool BIAS>
__global__ void __launch_bounds__(128, 2)
tgemm(const float* __restrict__ A, int lda,
      const float* __restrict__ B, int K,
      const float* __restrict__ bias,
      float* __restrict__ C, int ldc,
      int M, const int* __restrict__ mdev,
      int t, int L, const int* __restrict__ nbr,
      float* __restrict__ hout)
{
    if (mdev) M = *mdev;
    const int m0 = blockIdx.y * 128;
    if (m0 >= M) return;
    const int n0 = blockIdx.x * 128;

    extern __shared__ float smem[];
    const unsigned sbase = (unsigned)__cvta_generic_to_shared(smem);

    const int tid  = threadIdx.x;
    const int warp = tid >> 5, lane = tid & 31;
    const int r = lane >> 2, c = lane & 3;
    const int wm = (warp & 1) * 64;
    const int wn = (warp >> 1) * 64;

    // ldmatrix per-lane address bases (float index): group g supplies rows of
    // the g-th 8x4-tf32 fragment: g&1 -> +8 rows, g>>1 -> +4 cols.
    const int gql = lane >> 3, wql = lane & 7;
    const int a_lbase = (wm + (gql & 1) * 8 + wql) * PITCH + (gql >> 1) * 4;
    const int b_lbase = (wn + (gql & 1) * 8 + wql) * PITCH + (gql >> 1) * 4;

    float acc[4][8][4];
#pragma unroll
    for (int i = 0; i < 4; i++)
#pragma unroll
        for (int j = 0; j < 8; j++)
#pragma unroll
            for (int q = 0; q < 4; q++) acc[i][j][q] = 0.f;

    const int nk = K >> 5;

    auto load_stage = [&](int it, int stg) {
        int k0 = it << 5;
#pragma unroll
        for (int i = 0; i < 8; i++) {
            int q = tid + i * 128;
            int row = q >> 3, f4 = q & 7;
            unsigned soff = (unsigned)((stg * ASTG + row * PITCH + f4 * 4) * 4);
            const float* ga = A + (size_t)(m0 + row) * lda + k0 + f4 * 4;
            cpa16(sbase + soff, ga, ((m0 + row) < M) ? 16 : 0);
            const float* gb = B + (size_t)(n0 + row) * K + k0 + f4 * 4;
            cpa16(sbase + (unsigned)(2 * ASTG * 4) + soff, gb, 16);
        }
        cpa_commit();
    };

    load_stage(0, 0);

    for (int it = 0; it < nk; ++it) {
        if (it + 1 < nk) { load_stage(it + 1, (it + 1) & 1); cpa_wait<1>(); }
        else             { cpa_wait<0>(); }
        __syncthreads();

        const unsigned aoff = sbase + (unsigned)(((it & 1) * ASTG) * 4);
        const unsigned boff = sbase + (unsigned)(((2 + (it & 1)) * ASTG) * 4);
#pragma unroll
        for (int kk = 0; kk < 32; kk += 8) {
            unsigned ua[4][4], ub2[4][4];
#pragma unroll
            for (int mt = 0; mt < 4; mt++)
                ldm4(ua[mt], aoff + (unsigned)((a_lbase + mt * 16 * PITCH + kk) * 4));
#pragma unroll
            for (int a = 0; a < 4; a++)
                ldm4(ub2[a], boff + (unsigned)((b_lbase + a * 16 * PITCH + kk) * 4));
            // ub2[a] = { ub[2a][0], ub[2a+1][0], ub[2a][1], ub[2a+1][1] }
#pragma unroll
            for (int mt = 0; mt < 4; mt++)
#pragma unroll
                for (int nf = 0; nf < 8; nf++)
                    mma_tf32(acc[mt][nf],
                             ua[mt][0], ua[mt][1], ua[mt][2], ua[mt][3],
                             ub2[nf >> 1][nf & 1], ub2[nf >> 1][2 + (nf & 1)]);
        }
        __syncthreads();
    }

    if (EPI != 4) {
        const int cc2 = c * 2;
#pragma unroll
        for (int mt = 0; mt < 4; mt++) {
            int row0 = m0 + wm + mt * 16 + r;
#pragma unroll
            for (int nf = 0; nf < 8; nf++) {
                int col = n0 + wn + nf * 8 + cc2;
                float bx = 0.f, by = 0.f;
                if (BIAS) { bx = bias[col]; by = bias[col + 1]; }
#pragma unroll
                for (int h = 0; h < 2; h++) {
                    int row = row0 + h * 8;
                    if (row >= M) continue;
                    float vx = acc[mt][nf][h * 2 + 0] + bx;
                    float vy = acc[mt][nf][h * 2 + 1] + by;
                    if (EPI == 1 || EPI == 2) { vx = fmaxf(vx, 0.f); vy = fmaxf(vy, 0.f); }
                    if (EPI == 1 || EPI == 3) { vx = roundtf(vx); vy = roundtf(vy); }
                    if (EPI == 2) {
                        if (col < 512 || col >= 640)         vx = roundtf(vx);
                        if (col + 1 < 512 || col + 1 >= 640) vy = roundtf(vy);
                    }
                    *(float2*)(C + (size_t)row * ldc + col) = make_float2(vx, vy);
                }
            }
        }
    } else {
        // fused LSTM epilogue: stage full 128x128 gate tile in smem, then pointwise.
        float* gbuf = smem;   // 128 x 132 floats = 67584 <= 73728
        const int cc2 = c * 2;
#pragma unroll
        for (int mt = 0; mt < 4; mt++) {
            int lr0 = wm + mt * 16 + r;
#pragma unroll
            for (int nf = 0; nf < 8; nf++) {
                int col = wn + nf * 8 + cc2;
                gbuf[lr0 * 132 + col]           = acc[mt][nf][0];
                gbuf[lr0 * 132 + col + 1]       = acc[mt][nf][1];
                gbuf[(lr0 + 8) * 132 + col]     = acc[mt][nf][2];
                gbuf[(lr0 + 8) * 132 + col + 1] = acc[mt][nf][3];
            }
        }
        __syncthreads();
        const int jj0 = (tid & 3) * 8;
#pragma unroll
        for (int pass = 0; pass < 4; pass++) {
            int rl = pass * 32 + (tid >> 2);
            int row = m0 + rl;
            if (row < M) {
                int node = g_order[row];
                int idx  = nbr[(size_t)node * L + t];   // active rows => idx > 0
                const float* gx = (idx <= T_EDGES)
                    ? g_gxs + (size_t)(idx - 1) * NG
                    : g_gxo + (size_t)(idx - 1 - T_EDGES) * NG;
#pragma unroll
                for (int u = 0; u < 8; u++) {
                    int jj = jj0 + u;
                    float gi = gbuf[rl * 132 + jj]      + gx[n0 + jj]      + g_bias[n0 + jj];
                    float gf = gbuf[rl * 132 + 32 + jj] + gx[n0 + 32 + jj] + g_bias[n0 + 32 + jj];
                    float gg = gbuf[rl * 132 + 64 + jj] + gx[n0 + 64 + jj] + g_bias[n0 + 64 + jj];
                    float go = gbuf[rl * 132 + 96 + jj] + gx[n0 + 96 + jj] + g_bias[n0 + 96 + jj];
                    int j = (n0 >> 2) + jj;    // global hidden index
                    float cc = g_cs[(size_t)row * HH + j];
                    float c2 = sigm(gf) * cc + sigm(gi) * tanhf(gg);
                    float h2 = sigm(go) * tanhf(c2);
                    g_cs[(size_t)row * HH + j] = c2;
                    hout[(size_t)row * HH + j] = roundtf(h2);
                }
            }
        }
    }
}

// ---------------- prep / pointwise kernels -------------------------------------
__global__ void k_round(const float* __restrict__ src, float* __restrict__ dst, int n)
{
    int i = blockIdx.x * blockDim.x + threadIdx.x;
    if (i < n) dst[i] = roundtf(src[i]);
}

// permute rows of W[2048,512] by gate interleave and round
__global__ void k_perm_w(const float* __restrict__ W, float* __restrict__ out)
{
    int i = blockIdx.x * blockDim.x + threadIdx.x;
    if (i >= 2048 * 512) return;
    int p = i >> 9, k = i & 511;
    int g = (p >> 5) & 3, tg = p >> 7, jj = p & 31;
    int orig = g * 512 + tg * 32 + jj;
    out[i] = roundtf(W[(size_t)orig * 512 + k]);
}

__global__ void k_perm_bias(const float* __restrict__ bih, const float* __restrict__ bhh)
{
    int p = blockIdx.x * blockDim.x + threadIdx.x;
    if (p >= 2048) return;
    int g = (p >> 5) & 3, tg = p >> 7, jj = p & 31;
    int orig = g * 512 + tg * 32 + jj;
    g_bias[p] = bih[orig] + bhh[orig];
}

__global__ void k_zero_hist()
{
    int i = blockIdx.x * blockDim.x + threadIdx.x;
    if (i < HIST_SZ) g_hist[i] = 0;
}
__global__ void k_hist(const int* __restrict__ lengths)
{
    int n = blockIdx.x * blockDim.x + threadIdx.x;
    if (n < O_NODES) atomicAdd(&g_hist[lengths[n]], 1);
}
__global__ void k_scan(int L)
{
    int run = 0;
    for (int len = L; len >= 0; --len) {
        g_cursor[len] = run;
        g_cnt[len]    = run;
        run += g_hist[len];
    }
}
__global__ void k_scatter(const int* __restrict__ lengths)
{
    int n = blockIdx.x * blockDim.x + threadIdx.x;
    if (n >= O_NODES) return;
    int pos = atomicAdd(&g_cursor[lengths[n]], 1);
    g_order[pos] = n;
    g_pos[n] = pos;
}

__global__ void k_build_cur(const float* __restrict__ obj,
                            const float* __restrict__ pred,
                            const int* __restrict__ edges)
{
    int i = blockIdx.x * blockDim.x + threadIdx.x;
    if (i >= T_EDGES * 384) return;
    int e = i / 384, q = i - e * 384;
    float v;
    if (q < 128)       v = obj[(size_t)edges[2 * e] * 128 + q];
    else if (q < 256)  v = pred[(size_t)e * 128 + (q - 128)];
    else               v = obj[(size_t)edges[2 * e + 1] * 128 + (q - 256)];
    g_cur[(size_t)e * 384 + q] = roundtf(v);
}

__global__ void k_copy_newp(float* __restrict__ out)
{
    int i = blockIdx.x * blockDim.x + threadIdx.x;
    if (i >= T_EDGES * 32) return;
    int e = i / 32, q = i - e * 32;
    ((float4*)out)[(size_t)(O_NODES * 32) + (size_t)e * 32 + q] =
        ((const float4*)g_newt)[(size_t)e * 288 + 128 + q];
}

// step 0: x=0, h=0 -> gates = biases only; identical for all nodes
__global__ void k_step0a()
{
    int j = threadIdx.x;
    int tg = j >> 5, jj = j & 31;
    int base = tg * 128 + jj;
    float gi = g_bias[base];
    float gf = g_bias[base + 32];
    float gg = g_bias[base + 64];
    float go = g_bias[base + 96];
    float c1 = sigm(gi) * tanhf(gg);          // c0 = 0
    float h1 = sigm(go) * tanhf(c1);
    g_c1[j] = c1;
    g_h1[j] = roundtf(h1);
}
// step 0 "writes" buffer 1 (read by step 1)
__global__ void k_step0b()
{
    int i = blockIdx.x * blockDim.x + threadIdx.x;
    if (i >= O_NODES * HH) return;
    g_cs[i]  = g_c1[i & 511];
    g_hsB[i] = g_h1[i & 511];
}

// pooled[n] = hbuf[lengths[n] & 1] at sorted row pos[n]; prev appended
__global__ void k_build_pc(const int* __restrict__ lengths)
{
    int i = blockIdx.x * blockDim.x + threadIdx.x;
    if (i >= O_NODES * 256) return;
    int n = i >> 8, q = i & 255;
    float4 v;
    if (q < 128) {
        const float* hb = (lengths[n] & 1) ? g_hsB : g_hsA;
        v = ((const float4*)hb)[(size_t)g_pos[n] * 128 + q];
    } else {
        v = ((const float4*)g_prev)[(size_t)n * 128 + (q - 128)];
    }
    ((float4*)g_pc)[(size_t)n * 256 + q] = v;
}

// ---------------- launcher -----------------------------------------------------
extern "C" void kernel_launch(void* const* d_in, const int* in_sizes, int n_in,
                              void* d_out, int out_size)
{
    const float* obj    = (const float*)d_in[0];
    const float* pred   = (const float*)d_in[1];
    const int*   edges  = (const int*)  d_in[2];
    const int*   nbr    = (const int*)  d_in[3];
    const int*   lengths= (const int*)  d_in[4];
    const float* W1     = (const float*)d_in[5];
    const float* b1     = (const float*)d_in[6];
    const float* W2     = (const float*)d_in[7];
    const float* b2     = (const float*)d_in[8];
    const float* Wih    = (const float*)d_in[9];
    const float* Whh    = (const float*)d_in[10];
    const float* bih    = (const float*)d_in[11];
    const float* bhh    = (const float*)d_in[12];
    const float* Wproj  = (const float*)d_in[13];
    const float* bproj  = (const float*)d_in[14];
    const float* Wout   = (const float*)d_in[15];
    const float* bout   = (const float*)d_in[16];
    float* out = (float*)d_out;

    const int L = in_sizes[3] / O_NODES;

    float *p_cur, *p_mid, *p_newt, *p_gxs, *p_gxo, *p_hsA, *p_hsB, *p_prev, *p_pc, *p_obj32;
    float *p_w1, *p_w2, *p_wih, *p_whh, *p_wproj, *p_wout;
    int *p_cnt;
    cudaGetSymbolAddress((void**)&p_cur,   g_cur);
    cudaGetSymbolAddress((void**)&p_mid,   g_mid);
    cudaGetSymbolAddress((void**)&p_newt,  g_newt);
    cudaGetSymbolAddress((void**)&p_gxs,   g_gxs);
    cudaGetSymbolAddress((void**)&p_gxo,   g_gxo);
    cudaGetSymbolAddress((void**)&p_hsA,   g_hsA);
    cudaGetSymbolAddress((void**)&p_hsB,   g_hsB);
    cudaGetSymbolAddress((void**)&p_prev,  g_prev);
    cudaGetSymbolAddress((void**)&p_pc,    g_pc);
    cudaGetSymbolAddress((void**)&p_obj32, g_obj32);
    cudaGetSymbolAddress((void**)&p_w1,    g_w1r);
    cudaGetSymbolAddress((void**)&p_w2,    g_w2r);
    cudaGetSymbolAddress((void**)&p_wih,   g_wihr);
    cudaGetSymbolAddress((void**)&p_whh,   g_whhr);
    cudaGetSymbolAddress((void**)&p_wproj, g_wprojr);
    cudaGetSymbolAddress((void**)&p_wout,  g_woutr);
    cudaGetSymbolAddress((void**)&p_cnt,   g_cnt);

    cudaFuncSetAttribute(tgemm<0, false>, cudaFuncAttributeMaxDynamicSharedMemorySize, TG_SMEM);
    cudaFuncSetAttribute(tgemm<0, true >, cudaFuncAttributeMaxDynamicSharedMemorySize, TG_SMEM);
    cudaFuncSetAttribute(tgemm<1, true >, cudaFuncAttributeMaxDynamicSharedMemorySize, TG_SMEM);
    cudaFuncSetAttribute(tgemm<2, true >, cudaFuncAttributeMaxDynamicSharedMemorySize, TG_SMEM);
    cudaFuncSetAttribute(tgemm<3, true >, cudaFuncAttributeMaxDynamicSharedMemorySize, TG_SMEM);
    cudaFuncSetAttribute(tgemm<4, false>, cudaFuncAttributeMaxDynamicSharedMemorySize, TG_SMEM);

    const int MT_E = (T_EDGES + 127) / 128;   // 391
    const int MT_O = (O_NODES + 127) / 128;   // 79

    // weight prep (round to tf32; Wih/Whh permuted)
    k_round<<<(512 * 384 + 255) / 256, 256>>>(W1, p_w1, 512 * 384);
    k_round<<<(1152 * 512 + 255) / 256, 256>>>(W2, p_w2, 1152 * 512);
    k_perm_w<<<(2048 * 512 + 255) / 256, 256>>>(Wih, p_wih);
    k_perm_w<<<(2048 * 512 + 255) / 256, 256>>>(Whh, p_whh);
    k_round<<<(512 * 128 + 255) / 256, 256>>>(Wproj, p_wproj, 512 * 128);
    k_round<<<(128 * 1024 + 255) / 256, 256>>>(Wout, p_wout, 128 * 1024);
    k_round<<<(O_NODES * 128 + 255) / 256, 256>>>(obj, p_obj32, O_NODES * 128);
    k_perm_bias<<<8, 256>>>(bih, bhh);

    // node sort by length (descending)
    k_zero_hist<<<HIST_SZ / 256, 256>>>();
    k_hist<<<(O_NODES + 255) / 256, 256>>>(lengths);
    k_scan<<<1, 1>>>(L);
    k_scatter<<<(O_NODES + 255) / 256, 256>>>(lengths);

    // edge MLP
    k_build_cur<<<(T_EDGES * 384 + 255) / 256, 256>>>(obj, pred, edges);
    tgemm<1, true ><<<dim3(4, MT_E), 128, TG_SMEM>>>(p_cur, 384, p_w1, 384, b1, p_mid, 512, T_EDGES, nullptr, 0, 0, nullptr, nullptr);
    tgemm<2, true ><<<dim3(9, MT_E), 128, TG_SMEM>>>(p_mid, 512, p_w2, 512, b2, p_newt, 1152, T_EDGES, nullptr, 0, 0, nullptr, nullptr);
    k_copy_newp<<<(T_EDGES * 32 + 255) / 256, 256>>>(out);

    // LSTM input-gate precompute (permuted gate columns)
    tgemm<0, false><<<dim3(16, MT_E), 128, TG_SMEM>>>(p_newt,       1152, p_wih, 512, nullptr, p_gxs, NG, T_EDGES, nullptr, 0, 0, nullptr, nullptr);
    tgemm<0, false><<<dim3(16, MT_E), 128, TG_SMEM>>>(p_newt + 640, 1152, p_wih, 512, nullptr, p_gxo, NG, T_EDGES, nullptr, 0, 0, nullptr, nullptr);

    // prev = obj @ Wproj^T + bproj
    tgemm<3, true ><<<dim3(4, MT_O), 128, TG_SMEM>>>(p_obj32, 128, p_wproj, 128, bproj, p_prev, 512, O_NODES, nullptr, 0, 0, nullptr, nullptr);

    // LSTM step 0 closed form (writes buffer B), then fused steps t=1..L-1:
    // step t reads hbuf[t&1], writes hbuf[(t+1)&1]  (ping-pong, no intra-launch race)
    k_step0a<<<1, 512>>>();
    k_step0b<<<(O_NODES * HH + 255) / 256, 256>>>();
    for (int t = 1; t < L; ++t) {
        float* hin  = (t & 1) ? p_hsB : p_hsA;
        float* hout = (t & 1) ? p_hsA : p_hsB;
        tgemm<4, false><<<dim3(16, MT_O), 128, TG_SMEM>>>(hin, 512, p_whh, 512, nullptr, nullptr, 0, O_NODES, p_cnt + t, t, L, nbr, hout);
    }

    // new_obj = [pooled | prev] @ Wout^T + bout (exact epilogue)
    k_build_pc<<<(O_NODES * 256 + 255) / 256, 256>>>(lengths);
    tgemm<0, true ><<<dim3(1, MT_O), 128, TG_SMEM>>>(p_pc, 1024, p_wout, 1024, bout, out, 128, O_NODES, nullptr, 0, 0, nullptr, nullptr);
}